// round 2
// baseline (speedup 1.0000x reference)
#include <cuda_runtime.h>
#include <math.h>

// Problem constants
#define BB 4
#define SS 2048
#define EE 1024
#define HH 16
#define HD 64
#define MROWS (BB * SS)        // 8192
#define QKVN  (3 * EE)         // 3072

// Scratch (static device globals: allowed; no runtime allocation)
__device__ float g_qkv[MROWS * QKVN];   // [B*S, 3E]  (per-head interleaved q,k,v)
__device__ float g_attn[MROWS * EE];    // [B*S, E]   attention output, head-major cols

// ---------------------------------------------------------------------------
// GEMM (NT): C[M,N] = A[M,K] @ B[N,K]^T + bias[N]
// 64x64 tile, BK=16, 256 threads, 4x4 micro-tile per thread.
// ---------------------------------------------------------------------------
__global__ __launch_bounds__(256) void sgemm_nt_kernel(
    const float* __restrict__ A, const float* __restrict__ Bm,
    const float* __restrict__ bias, float* __restrict__ C,
    int M, int N, int K)
{
    __shared__ float As[16][64];   // [k][m]
    __shared__ float Bs[16][64];   // [k][n]

    const int t  = threadIdx.x;
    const int bm = blockIdx.y * 64;
    const int bn = blockIdx.x * 64;

    const int lr = t >> 2;          // 0..63 : row within tile for loading
    const int lk = (t & 3) << 2;    // 0,4,8,12 : k offset for loading

    const int tx = t & 15;          // 0..15
    const int ty = t >> 4;          // 0..15

    float acc[4][4] = {};

    const float* Ap = A  + (size_t)(bm + lr) * K + lk;
    const float* Bp = Bm + (size_t)(bn + lr) * K + lk;

    for (int k0 = 0; k0 < K; k0 += 16) {
        float4 va = *reinterpret_cast<const float4*>(Ap + k0);
        float4 vb = *reinterpret_cast<const float4*>(Bp + k0);
        As[lk + 0][lr] = va.x; As[lk + 1][lr] = va.y;
        As[lk + 2][lr] = va.z; As[lk + 3][lr] = va.w;
        Bs[lk + 0][lr] = vb.x; Bs[lk + 1][lr] = vb.y;
        Bs[lk + 2][lr] = vb.z; Bs[lk + 3][lr] = vb.w;
        __syncthreads();

        #pragma unroll
        for (int k = 0; k < 16; ++k) {
            float4 a = *reinterpret_cast<const float4*>(&As[k][ty << 2]);
            float4 b = *reinterpret_cast<const float4*>(&Bs[k][tx << 2]);
            float av[4] = {a.x, a.y, a.z, a.w};
            float bv[4] = {b.x, b.y, b.z, b.w};
            #pragma unroll
            for (int i = 0; i < 4; ++i)
                #pragma unroll
                for (int j = 0; j < 4; ++j)
                    acc[i][j] += av[i] * bv[j];
        }
        __syncthreads();
    }

    const int col = bn + (tx << 2);
    float4 bsv = *reinterpret_cast<const float4*>(bias + col);
    #pragma unroll
    for (int i = 0; i < 4; ++i) {
        const int row = bm + (ty << 2) + i;
        float4 o;
        o.x = acc[i][0] + bsv.x;
        o.y = acc[i][1] + bsv.y;
        o.z = acc[i][2] + bsv.z;
        o.w = acc[i][3] + bsv.w;
        *reinterpret_cast<float4*>(C + (size_t)row * N + col) = o;
    }
}

// ---------------------------------------------------------------------------
// Flash attention (causal, online softmax).
// Grid: (S/64, H, B). Block: 256 threads.
// Thread t handles query row r = t/4; quad q4 = t%4 owns a 16-wide chunk of
// head-dim for Q/O. Score row (64 wide) is fully materialized per thread via
// quad shfl-reduction, so softmax needs no cross-thread reduction.
// ---------------------------------------------------------------------------
__global__ __launch_bounds__(256) void attn_kernel(
    const float* __restrict__ qkv, float* __restrict__ attn_out)
{
    __shared__ float Ks[64][64];
    __shared__ float Vs[64][64];

    const int qt = blockIdx.x;
    const int h  = blockIdx.y;
    const int b  = blockIdx.z;

    const int t  = threadIdx.x;
    const int r  = t >> 2;        // query row within tile (0..63)
    const int q4 = t & 3;         // quad lane (0..3)

    const int qs = qt * 64 + r;   // absolute query position
    const size_t base = (size_t)b * SS * QKVN;
    const int hoff = h * (3 * HD);

    // Load my 16-wide Q chunk into registers
    float Qreg[16];
    {
        const float* qrow = qkv + base + (size_t)qs * QKVN + hoff + q4 * 16;
        #pragma unroll
        for (int i = 0; i < 16; i += 4) {
            float4 v = *reinterpret_cast<const float4*>(qrow + i);
            Qreg[i] = v.x; Qreg[i + 1] = v.y; Qreg[i + 2] = v.z; Qreg[i + 3] = v.w;
        }
    }

    float m = -1e30f, l = 0.0f;
    float O[16];
    #pragma unroll
    for (int i = 0; i < 16; ++i) O[i] = 0.0f;

    const float inv_scale = 0.125f;   // 1/sqrt(64)

    for (int kt = 0; kt <= qt; ++kt) {
        // Cooperative load of K and V tiles (64x64 each)
        {
            const float* krow = qkv + base + (size_t)(kt * 64 + r) * QKVN + hoff + HD + q4 * 16;
            const float* vrow = krow + HD;
            #pragma unroll
            for (int i = 0; i < 16; i += 4) {
                *reinterpret_cast<float4*>(&Ks[r][q4 * 16 + i]) =
                    *reinterpret_cast<const float4*>(krow + i);
                *reinterpret_cast<float4*>(&Vs[r][q4 * 16 + i]) =
                    *reinterpret_cast<const float4*>(vrow + i);
            }
        }
        __syncthreads();

        // Partial scores over my 16-dim chunk, for all 64 keys
        float s[64];
        #pragma unroll
        for (int c = 0; c < 64; ++c) {
            const float4* kp = reinterpret_cast<const float4*>(&Ks[c][q4 * 16]);
            float4 k0 = kp[0], k1 = kp[1], k2 = kp[2], k3 = kp[3];
            float acc;
            acc  = Qreg[0]  * k0.x; acc += Qreg[1]  * k0.y;
            acc += Qreg[2]  * k0.z; acc += Qreg[3]  * k0.w;
            acc += Qreg[4]  * k1.x; acc += Qreg[5]  * k1.y;
            acc += Qreg[6]  * k1.z; acc += Qreg[7]  * k1.w;
            acc += Qreg[8]  * k2.x; acc += Qreg[9]  * k2.y;
            acc += Qreg[10] * k2.z; acc += Qreg[11] * k2.w;
            acc += Qreg[12] * k3.x; acc += Qreg[13] * k3.y;
            acc += Qreg[14] * k3.z; acc += Qreg[15] * k3.w;
            s[c] = acc;
        }
        // Quad reduction -> every lane of the quad holds the full dot product
        #pragma unroll
        for (int c = 0; c < 64; ++c) {
            s[c] += __shfl_xor_sync(0xffffffffu, s[c], 1);
            s[c] += __shfl_xor_sync(0xffffffffu, s[c], 2);
        }

        // Scale + causal mask (diagonal tile only)
        if (kt == qt) {
            #pragma unroll
            for (int c = 0; c < 64; ++c)
                s[c] = (c <= r) ? s[c] * inv_scale : -1e30f;
        } else {
            #pragma unroll
            for (int c = 0; c < 64; ++c)
                s[c] *= inv_scale;
        }

        // Online softmax update
        float tmax = -1e30f;
        #pragma unroll
        for (int c = 0; c < 64; ++c) tmax = fmaxf(tmax, s[c]);
        const float mnew = fmaxf(m, tmax);
        const float corr = __expf(m - mnew);
        l *= corr;
        #pragma unroll
        for (int i = 0; i < 16; ++i) O[i] *= corr;
        #pragma unroll
        for (int c = 0; c < 64; ++c) {
            s[c] = __expf(s[c] - mnew);
            l += s[c];
        }
        m = mnew;

        // O += P @ V  (my 16-dim chunk)
        #pragma unroll
        for (int c = 0; c < 64; ++c) {
            const float4* vp = reinterpret_cast<const float4*>(&Vs[c][q4 * 16]);
            float4 v0 = vp[0], v1 = vp[1], v2 = vp[2], v3 = vp[3];
            const float p = s[c];
            O[0]  += p * v0.x; O[1]  += p * v0.y; O[2]  += p * v0.z; O[3]  += p * v0.w;
            O[4]  += p * v1.x; O[5]  += p * v1.y; O[6]  += p * v1.z; O[7]  += p * v1.w;
            O[8]  += p * v2.x; O[9]  += p * v2.y; O[10] += p * v2.z; O[11] += p * v2.w;
            O[12] += p * v3.x; O[13] += p * v3.y; O[14] += p * v3.z; O[15] += p * v3.w;
        }
        __syncthreads();
    }

    const float invl = 1.0f / l;
    float* orow = attn_out + (size_t)(b * SS + qs) * EE + h * HD + q4 * 16;
    #pragma unroll
    for (int i = 0; i < 16; i += 4) {
        float4 o;
        o.x = O[i] * invl; o.y = O[i + 1] * invl;
        o.z = O[i + 2] * invl; o.w = O[i + 3] * invl;
        *reinterpret_cast<float4*>(orow + i) = o;
    }
}

// ---------------------------------------------------------------------------
// Launch
// ---------------------------------------------------------------------------
extern "C" void kernel_launch(void* const* d_in, const int* in_sizes, int n_in,
                              void* d_out, int out_size)
{
    const float* x      = (const float*)d_in[0];
    const float* qkv_w  = (const float*)d_in[1];
    const float* qkv_b  = (const float*)d_in[2];
    const float* out_w  = (const float*)d_in[3];
    const float* out_b  = (const float*)d_in[4];
    float* out = (float*)d_out;

    float* qkv_ptr = nullptr;
    float* attn_ptr = nullptr;
    cudaGetSymbolAddress((void**)&qkv_ptr, g_qkv);
    cudaGetSymbolAddress((void**)&attn_ptr, g_attn);

    // 1) QKV projection: [8192,1024] x [3072,1024]^T -> [8192,3072]
    {
        dim3 grid(QKVN / 64, MROWS / 64);
        sgemm_nt_kernel<<<grid, 256>>>(x, qkv_w, qkv_b, qkv_ptr, MROWS, QKVN, EE);
    }
    // 2) Causal flash attention -> [8192,1024]
    {
        dim3 grid(SS / 64, HH, BB);
        attn_kernel<<<grid, 256>>>(qkv_ptr, attn_ptr);
    }
    // 3) Output projection: [8192,1024] x [1024,1024]^T -> [8192,1024]
    {
        dim3 grid(EE / 64, MROWS / 64);
        sgemm_nt_kernel<<<grid, 256>>>(attn_ptr, out_w, out_b, out, MROWS, EE, EE);
    }
}

// round 5
// speedup vs baseline: 1.2497x; 1.2497x over previous
#include <cuda_runtime.h>
#include <cuda_bf16.h>
#include <math.h>
#include <stdint.h>

// Problem constants
#define BB 4
#define SS 2048
#define EE 1024
#define HH 16
#define HD 64
#define MROWS (BB * SS)        // 8192
#define QKVN  (3 * EE)         // 3072
#define KSPLIT (3 * EE)        // split-K' = 3072

// GEMM config: CTA 128x128, BK=32 bf16, 8 warps (4Mx2N), warp tile 32x64
#define BKI 32
#define NSTG 3
#define ROWPITCH 80                       // 40 bf16 per row (64B data + 16B pad)
#define ATILE_B (128 * ROWPITCH)          // 10240 bytes
#define STG_B   (2 * ATILE_B)             // 20480 bytes per stage (A+B)
#define GEMM_SMEM (NSTG * STG_B)          // 61440

// Scratch (static device globals)
__device__ float          g_qkv[MROWS * QKVN];
__device__ float          g_attn[MROWS * EE];
__device__ __nv_bfloat16  g_a1[MROWS * KSPLIT];
__device__ __nv_bfloat16  g_b1[QKVN  * KSPLIT];
__device__ __nv_bfloat16  g_a2[MROWS * KSPLIT];
__device__ __nv_bfloat16  g_b2[EE    * KSPLIT];

// ---------------------------------------------------------------------------
// PTX helpers (plain compute_103-legal: cp.async, ldmatrix, mma.sync)
// ---------------------------------------------------------------------------
__device__ __forceinline__ uint32_t smem_u32(const void* p) {
    uint32_t a;
    asm("{ .reg .u64 t; cvta.to.shared.u64 t, %1; cvt.u32.u64 %0, t; }" : "=r"(a) : "l"(p));
    return a;
}
__device__ __forceinline__ void cp_async16(uint32_t dst, const void* src) {
    asm volatile("cp.async.cg.shared.global [%0], [%1], 16;" :: "r"(dst), "l"(src));
}
__device__ __forceinline__ void cp_commit() {
    asm volatile("cp.async.commit_group;");
}
template<int N>
__device__ __forceinline__ void cp_wait() {
    asm volatile("cp.async.wait_group %0;" :: "n"(N));
}
__device__ __forceinline__ void ldmx4(uint32_t* r, uint32_t addr) {
    asm volatile("ldmatrix.sync.aligned.m8n8.x4.shared.b16 {%0,%1,%2,%3}, [%4];"
        : "=r"(r[0]), "=r"(r[1]), "=r"(r[2]), "=r"(r[3]) : "r"(addr));
}
__device__ __forceinline__ void mma16816(float* d, const uint32_t* a, const uint32_t* b) {
    asm volatile(
        "mma.sync.aligned.m16n8k16.row.col.f32.bf16.bf16.f32 "
        "{%0,%1,%2,%3}, {%4,%5,%6,%7}, {%8,%9}, {%0,%1,%2,%3};"
        : "+f"(d[0]), "+f"(d[1]), "+f"(d[2]), "+f"(d[3])
        : "r"(a[0]), "r"(a[1]), "r"(a[2]), "r"(a[3]), "r"(b[0]), "r"(b[1]));
}

// ---------------------------------------------------------------------------
// Split prep: fp32 -> bf16 [hi|lo|hi] (A) or [hi|hi|lo] (B); dst [rows, 3K]
// ---------------------------------------------------------------------------
template<int PATTERN>
__global__ __launch_bounds__(256) void split_kernel(
    const float* __restrict__ src, __nv_bfloat16* __restrict__ dst, int K)
{
    const int idx = blockIdx.x * 256 + threadIdx.x;
    const int pairsPerRow = K >> 1;
    const int m = idx / pairsPerRow;
    const int k = (idx - m * pairsPerRow) << 1;
    const float2 v = *reinterpret_cast<const float2*>(src + (size_t)m * K + k);
    __nv_bfloat16 h0 = __float2bfloat16_rn(v.x);
    __nv_bfloat16 h1 = __float2bfloat16_rn(v.y);
    __nv_bfloat16 l0 = __float2bfloat16_rn(v.x - __bfloat162float(h0));
    __nv_bfloat16 l1 = __float2bfloat16_rn(v.y - __bfloat162float(h1));
    __nv_bfloat162 hi; hi.x = h0; hi.y = h1;
    __nv_bfloat162 lo; lo.x = l0; lo.y = l1;
    __nv_bfloat162* base = reinterpret_cast<__nv_bfloat162*>(dst + (size_t)m * 3 * K);
    const int kp = k >> 1;
    if (PATTERN == 0) { base[kp] = hi; base[(K >> 1) + kp] = lo; base[K + kp] = hi; }
    else              { base[kp] = hi; base[(K >> 1) + kp] = hi; base[K + kp] = lo; }
}

// ---------------------------------------------------------------------------
// bf16 mma.sync GEMM: C[M,N] = A'[M,K'] @ B'[N,K']^T + bias[N]
// ---------------------------------------------------------------------------
__device__ __forceinline__ void load_stage(
    uint32_t sstage, const __nv_bfloat16* __restrict__ A,
    const __nv_bfloat16* __restrict__ B,
    int bm, int bn, int k0, int Kel, int tid)
{
    #pragma unroll
    for (int i = 0; i < 2; ++i) {
        const int idx = tid + i * 256;
        const int row = idx >> 2, ch = idx & 3;
        cp_async16(sstage + row * ROWPITCH + ch * 16,
                   A + (size_t)(bm + row) * Kel + k0 + ch * 8);
        cp_async16(sstage + ATILE_B + row * ROWPITCH + ch * 16,
                   B + (size_t)(bn + row) * Kel + k0 + ch * 8);
    }
}

__global__ __launch_bounds__(256) void gemm_mma(
    const __nv_bfloat16* __restrict__ A, const __nv_bfloat16* __restrict__ B,
    const float* __restrict__ bias, float* __restrict__ C,
    int N, int Kel)
{
    extern __shared__ __align__(128) char smem[];
    const uint32_t sb = smem_u32(smem);
    const int tid  = threadIdx.x;
    const int lane = tid & 31;
    const int wid  = tid >> 5;
    const int wm   = wid >> 1;          // 0..3
    const int wn   = wid & 1;           // 0..1
    const int bm = blockIdx.y * 128;
    const int bn = blockIdx.x * 128;
    const int kIters = Kel / BKI;       // 96

    // ldmatrix byte offsets within a stage
    uint32_t aOff[2];
    {
        const int arow = wm * 32 + (lane & 15);
        #pragma unroll
        for (int t = 0; t < 2; ++t)
            aOff[t] = (uint32_t)((arow + t * 16) * ROWPITCH + (lane >> 4) * 16);
    }
    uint32_t bOff[4];
    {
        #pragma unroll
        for (int p = 0; p < 4; ++p) {
            const int brow = wn * 64 + p * 16 + (lane & 7) + ((lane >> 4) & 1) * 8;
            bOff[p] = (uint32_t)(ATILE_B + brow * ROWPITCH + ((lane >> 3) & 1) * 16);
        }
    }

    float acc[2][8][4];
    #pragma unroll
    for (int mt = 0; mt < 2; ++mt)
        #pragma unroll
        for (int nt = 0; nt < 8; ++nt)
            #pragma unroll
            for (int r = 0; r < 4; ++r) acc[mt][nt][r] = 0.0f;

    // prefetch NSTG-1 stages
    #pragma unroll
    for (int s = 0; s < NSTG - 1; ++s) {
        load_stage(sb + s * STG_B, A, B, bm, bn, s * BKI, Kel, tid);
        cp_commit();
    }
    cp_wait<NSTG - 2>();
    __syncthreads();

    int cur = 0;
    for (int i = 0; i < kIters; ++i) {
        // issue load for iter i+NSTG-1 into the slot freed at end of iter i-1
        if (i + NSTG - 1 < kIters) {
            const int s = (cur + NSTG - 1) % NSTG;
            load_stage(sb + s * STG_B, A, B, bm, bn, (i + NSTG - 1) * BKI, Kel, tid);
        }
        cp_commit();

        const uint32_t st = sb + cur * STG_B;
        #pragma unroll
        for (int kb = 0; kb < 2; ++kb) {
            uint32_t a[2][4], br[8][2];
            #pragma unroll
            for (int t = 0; t < 2; ++t)
                ldmx4(a[t], st + aOff[t] + kb * 32);
            #pragma unroll
            for (int p = 0; p < 4; ++p) {
                uint32_t r[4];
                ldmx4(r, st + bOff[p] + kb * 32);
                br[p * 2 + 0][0] = r[0]; br[p * 2 + 0][1] = r[1];
                br[p * 2 + 1][0] = r[2]; br[p * 2 + 1][1] = r[3];
            }
            #pragma unroll
            for (int mt = 0; mt < 2; ++mt)
                #pragma unroll
                for (int nt = 0; nt < 8; ++nt)
                    mma16816(acc[mt][nt], a[mt], br[nt]);
        }

        cp_wait<NSTG - 2>();
        __syncthreads();
        cur = (cur + 1) % NSTG;
    }

    // epilogue: direct stores + bias
    const int g  = lane >> 2;
    const int tq = lane & 3;
    #pragma unroll
    for (int mt = 0; mt < 2; ++mt) {
        #pragma unroll
        for (int rh = 0; rh < 2; ++rh) {
            const int row = bm + wm * 32 + mt * 16 + g + rh * 8;
            float* crow = C + (size_t)row * N;
            #pragma unroll
            for (int nt = 0; nt < 8; ++nt) {
                const int col = bn + wn * 64 + nt * 8 + tq * 2;
                float2 bs = *reinterpret_cast<const float2*>(bias + col);
                float2 o;
                o.x = acc[mt][nt][rh * 2 + 0] + bs.x;
                o.y = acc[mt][nt][rh * 2 + 1] + bs.y;
                *reinterpret_cast<float2*>(crow + col) = o;
            }
        }
    }
}

// ---------------------------------------------------------------------------
// Flash attention (unchanged, known-passing)
// ---------------------------------------------------------------------------
__global__ __launch_bounds__(256) void attn_kernel(
    const float* __restrict__ qkv, float* __restrict__ attn_out)
{
    __shared__ float Ks[64][64];
    __shared__ float Vs[64][64];

    const int qt = blockIdx.x;
    const int h  = blockIdx.y;
    const int b  = blockIdx.z;

    const int t  = threadIdx.x;
    const int r  = t >> 2;
    const int q4 = t & 3;

    const int qs = qt * 64 + r;
    const size_t base = (size_t)b * SS * QKVN;
    const int hoff = h * (3 * HD);

    float Qreg[16];
    {
        const float* qrow = qkv + base + (size_t)qs * QKVN + hoff + q4 * 16;
        #pragma unroll
        for (int i = 0; i < 16; i += 4) {
            float4 v = *reinterpret_cast<const float4*>(qrow + i);
            Qreg[i] = v.x; Qreg[i + 1] = v.y; Qreg[i + 2] = v.z; Qreg[i + 3] = v.w;
        }
    }

    float m = -1e30f, l = 0.0f;
    float O[16];
    #pragma unroll
    for (int i = 0; i < 16; ++i) O[i] = 0.0f;

    const float inv_scale = 0.125f;

    for (int kt = 0; kt <= qt; ++kt) {
        {
            const float* krow = qkv + base + (size_t)(kt * 64 + r) * QKVN + hoff + HD + q4 * 16;
            const float* vrow = krow + HD;
            #pragma unroll
            for (int i = 0; i < 16; i += 4) {
                *reinterpret_cast<float4*>(&Ks[r][q4 * 16 + i]) =
                    *reinterpret_cast<const float4*>(krow + i);
                *reinterpret_cast<float4*>(&Vs[r][q4 * 16 + i]) =
                    *reinterpret_cast<const float4*>(vrow + i);
            }
        }
        __syncthreads();

        float s[64];
        #pragma unroll
        for (int c = 0; c < 64; ++c) {
            const float4* kp = reinterpret_cast<const float4*>(&Ks[c][q4 * 16]);
            float4 k0 = kp[0], k1 = kp[1], k2 = kp[2], k3 = kp[3];
            float acc;
            acc  = Qreg[0]  * k0.x; acc += Qreg[1]  * k0.y;
            acc += Qreg[2]  * k0.z; acc += Qreg[3]  * k0.w;
            acc += Qreg[4]  * k1.x; acc += Qreg[5]  * k1.y;
            acc += Qreg[6]  * k1.z; acc += Qreg[7]  * k1.w;
            acc += Qreg[8]  * k2.x; acc += Qreg[9]  * k2.y;
            acc += Qreg[10] * k2.z; acc += Qreg[11] * k2.w;
            acc += Qreg[12] * k3.x; acc += Qreg[13] * k3.y;
            acc += Qreg[14] * k3.z; acc += Qreg[15] * k3.w;
            s[c] = acc;
        }
        #pragma unroll
        for (int c = 0; c < 64; ++c) {
            s[c] += __shfl_xor_sync(0xffffffffu, s[c], 1);
            s[c] += __shfl_xor_sync(0xffffffffu, s[c], 2);
        }

        if (kt == qt) {
            #pragma unroll
            for (int c = 0; c < 64; ++c)
                s[c] = (c <= r) ? s[c] * inv_scale : -1e30f;
        } else {
            #pragma unroll
            for (int c = 0; c < 64; ++c)
                s[c] *= inv_scale;
        }

        float tmax = -1e30f;
        #pragma unroll
        for (int c = 0; c < 64; ++c) tmax = fmaxf(tmax, s[c]);
        const float mnew = fmaxf(m, tmax);
        const float corr = __expf(m - mnew);
        l *= corr;
        #pragma unroll
        for (int i = 0; i < 16; ++i) O[i] *= corr;
        #pragma unroll
        for (int c = 0; c < 64; ++c) {
            s[c] = __expf(s[c] - mnew);
            l += s[c];
        }
        m = mnew;

        #pragma unroll
        for (int c = 0; c < 64; ++c) {
            const float4* vp = reinterpret_cast<const float4*>(&Vs[c][q4 * 16]);
            float4 v0 = vp[0], v1 = vp[1], v2 = vp[2], v3 = vp[3];
            const float p = s[c];
            O[0]  += p * v0.x; O[1]  += p * v0.y; O[2]  += p * v0.z; O[3]  += p * v0.w;
            O[4]  += p * v1.x; O[5]  += p * v1.y; O[6]  += p * v1.z; O[7]  += p * v1.w;
            O[8]  += p * v2.x; O[9]  += p * v2.y; O[10] += p * v2.z; O[11] += p * v2.w;
            O[12] += p * v3.x; O[13] += p * v3.y; O[14] += p * v3.z; O[15] += p * v3.w;
        }
        __syncthreads();
    }

    const float invl = 1.0f / l;
    float* orow = attn_out + (size_t)(b * SS + qs) * EE + h * HD + q4 * 16;
    #pragma unroll
    for (int i = 0; i < 16; i += 4) {
        float4 o;
        o.x = O[i] * invl; o.y = O[i + 1] * invl;
        o.z = O[i + 2] * invl; o.w = O[i + 3] * invl;
        *reinterpret_cast<float4*>(orow + i) = o;
    }
}

// ---------------------------------------------------------------------------
// Launch
// ---------------------------------------------------------------------------
extern "C" void kernel_launch(void* const* d_in, const int* in_sizes, int n_in,
                              void* d_out, int out_size)
{
    const float* x      = (const float*)d_in[0];
    const float* qkv_w  = (const float*)d_in[1];
    const float* qkv_b  = (const float*)d_in[2];
    const float* out_w  = (const float*)d_in[3];
    const float* out_b  = (const float*)d_in[4];
    float* out = (float*)d_out;

    float *qkv_ptr, *attn_ptr;
    __nv_bfloat16 *a1, *b1, *a2, *b2;
    cudaGetSymbolAddress((void**)&qkv_ptr, g_qkv);
    cudaGetSymbolAddress((void**)&attn_ptr, g_attn);
    cudaGetSymbolAddress((void**)&a1, g_a1);
    cudaGetSymbolAddress((void**)&b1, g_b1);
    cudaGetSymbolAddress((void**)&a2, g_a2);
    cudaGetSymbolAddress((void**)&b2, g_b2);

    cudaFuncSetAttribute(gemm_mma, cudaFuncAttributeMaxDynamicSharedMemorySize, GEMM_SMEM);

    // 1) split prep for proj1
    split_kernel<0><<<MROWS * EE / 512, 256>>>(x, a1, EE);
    split_kernel<1><<<QKVN  * EE / 512, 256>>>(qkv_w, b1, EE);

    // 2) QKV projection: [8192,3072] = A1' @ B1'^T + qkv_b
    {
        dim3 grid(QKVN / 128, MROWS / 128);
        gemm_mma<<<grid, 256, GEMM_SMEM>>>(a1, b1, qkv_b, qkv_ptr, QKVN, KSPLIT);
    }

    // 3) Causal flash attention -> [8192,1024]
    {
        dim3 grid(SS / 64, HH, BB);
        attn_kernel<<<grid, 256>>>(qkv_ptr, attn_ptr);
    }

    // 4) split prep for proj2
    split_kernel<0><<<MROWS * EE / 512, 256>>>(attn_ptr, a2, EE);
    split_kernel<1><<<EE    * EE / 512, 256>>>(out_w, b2, EE);

    // 5) Output projection: [8192,1024] = A2' @ B2'^T + out_b
    {
        dim3 grid(EE / 128, MROWS / 128);
        gemm_mma<<<grid, 256, GEMM_SMEM>>>(a2, b2, out_b, out, EE, KSPLIT);
    }
}

// round 6
// speedup vs baseline: 5.6174x; 4.4952x over previous
#include <cuda_runtime.h>
#include <cuda_bf16.h>
#include <math.h>
#include <stdint.h>

// Problem constants
#define BB 4
#define SS 2048
#define EE 1024
#define HH 16
#define HD 64
#define MROWS (BB * SS)        // 8192
#define QKVN  (3 * EE)         // 3072
#define KSPLIT (3 * EE)        // split-K' = 3072

// GEMM config: CTA 128x128, BK=32 bf16, 8 warps (4Mx2N), warp tile 32x64
#define BKI 32
#define NSTG 3
#define ROWPITCH 80
#define ATILE_B (128 * ROWPITCH)
#define STG_B   (2 * ATILE_B)
#define GEMM_SMEM (NSTG * STG_B)

// Attention config: k-tile 64 keys, rows padded to 144B
#define AT_ROWP 144                      // bytes per smem row (64 bf16 = 128B + 16B pad)
#define AT_TILE_B (64 * AT_ROWP)         // 9216 B per tile (Khi/Klo/Vhi/Vlo)
#define AT_STG_B (4 * AT_TILE_B)         // 36864 B per stage
#define AT_NSTG 3
#define ATT_SMEM (AT_NSTG * AT_STG_B)    // 110592 B

// Scratch (static device globals)
__device__ float          g_qkv[MROWS * QKVN];
__device__ float          g_attn[MROWS * EE];
__device__ __nv_bfloat16  g_a1[MROWS * KSPLIT];
__device__ __nv_bfloat16  g_b1[QKVN  * KSPLIT];
__device__ __nv_bfloat16  g_a2[MROWS * KSPLIT];
__device__ __nv_bfloat16  g_b2[EE    * KSPLIT];
// per-head attention operands [B*H, S, 64]
__device__ __nv_bfloat16  g_Qh[BB * HH * SS * HD];
__device__ __nv_bfloat16  g_Ql[BB * HH * SS * HD];
__device__ __nv_bfloat16  g_Kh[BB * HH * SS * HD];
__device__ __nv_bfloat16  g_Kl[BB * HH * SS * HD];
__device__ __nv_bfloat16  g_Vh[BB * HH * SS * HD];
__device__ __nv_bfloat16  g_Vl[BB * HH * SS * HD];

// ---------------------------------------------------------------------------
// PTX helpers (plain compute_103-legal)
// ---------------------------------------------------------------------------
__device__ __forceinline__ uint32_t smem_u32(const void* p) {
    uint32_t a;
    asm("{ .reg .u64 t; cvta.to.shared.u64 t, %1; cvt.u32.u64 %0, t; }" : "=r"(a) : "l"(p));
    return a;
}
__device__ __forceinline__ void cp_async16(uint32_t dst, const void* src) {
    asm volatile("cp.async.cg.shared.global [%0], [%1], 16;" :: "r"(dst), "l"(src));
}
__device__ __forceinline__ void cp_commit() {
    asm volatile("cp.async.commit_group;");
}
template<int N>
__device__ __forceinline__ void cp_wait() {
    asm volatile("cp.async.wait_group %0;" :: "n"(N));
}
__device__ __forceinline__ void ldmx4(uint32_t* r, uint32_t addr) {
    asm volatile("ldmatrix.sync.aligned.m8n8.x4.shared.b16 {%0,%1,%2,%3}, [%4];"
        : "=r"(r[0]), "=r"(r[1]), "=r"(r[2]), "=r"(r[3]) : "r"(addr));
}
__device__ __forceinline__ void ldmx4t(uint32_t* r, uint32_t addr) {
    asm volatile("ldmatrix.sync.aligned.m8n8.x4.trans.shared.b16 {%0,%1,%2,%3}, [%4];"
        : "=r"(r[0]), "=r"(r[1]), "=r"(r[2]), "=r"(r[3]) : "r"(addr));
}
__device__ __forceinline__ void mma16816(float* d, const uint32_t* a, const uint32_t* b) {
    asm volatile(
        "mma.sync.aligned.m16n8k16.row.col.f32.bf16.bf16.f32 "
        "{%0,%1,%2,%3}, {%4,%5,%6,%7}, {%8,%9}, {%0,%1,%2,%3};"
        : "+f"(d[0]), "+f"(d[1]), "+f"(d[2]), "+f"(d[3])
        : "r"(a[0]), "r"(a[1]), "r"(a[2]), "r"(a[3]), "r"(b[0]), "r"(b[1]));
}
__device__ __forceinline__ uint32_t pack_bf2(float a, float b) {
    __nv_bfloat162 t;
    t.x = __float2bfloat16_rn(a);
    t.y = __float2bfloat16_rn(b);
    return *reinterpret_cast<uint32_t*>(&t);
}

// ---------------------------------------------------------------------------
// Split prep: fp32 -> bf16 [hi|lo|hi] (A) or [hi|hi|lo] (B); dst [rows, 3K]
// ---------------------------------------------------------------------------
template<int PATTERN>
__global__ __launch_bounds__(256) void split_kernel(
    const float* __restrict__ src, __nv_bfloat16* __restrict__ dst, int K)
{
    const int idx = blockIdx.x * 256 + threadIdx.x;
    const int pairsPerRow = K >> 1;
    const int m = idx / pairsPerRow;
    const int k = (idx - m * pairsPerRow) << 1;
    const float2 v = *reinterpret_cast<const float2*>(src + (size_t)m * K + k);
    __nv_bfloat16 h0 = __float2bfloat16_rn(v.x);
    __nv_bfloat16 h1 = __float2bfloat16_rn(v.y);
    __nv_bfloat16 l0 = __float2bfloat16_rn(v.x - __bfloat162float(h0));
    __nv_bfloat16 l1 = __float2bfloat16_rn(v.y - __bfloat162float(h1));
    __nv_bfloat162 hi; hi.x = h0; hi.y = h1;
    __nv_bfloat162 lo; lo.x = l0; lo.y = l1;
    __nv_bfloat162* base = reinterpret_cast<__nv_bfloat162*>(dst + (size_t)m * 3 * K);
    const int kp = k >> 1;
    if (PATTERN == 0) { base[kp] = hi; base[(K >> 1) + kp] = lo; base[K + kp] = hi; }
    else              { base[kp] = hi; base[(K >> 1) + kp] = hi; base[K + kp] = lo; }
}

// ---------------------------------------------------------------------------
// QKV converter: g_qkv fp32 [B*S, 3E] -> per-head hi/lo [B*H, S, 64]
// Q pre-scaled by 0.125 (exact). One thread per float4.
// ---------------------------------------------------------------------------
__global__ __launch_bounds__(256) void qkv_convert(
    const float* __restrict__ qkv,
    __nv_bfloat16* __restrict__ Qh, __nv_bfloat16* __restrict__ Ql,
    __nv_bfloat16* __restrict__ Kh, __nv_bfloat16* __restrict__ Kl,
    __nv_bfloat16* __restrict__ Vh, __nv_bfloat16* __restrict__ Vl)
{
    const int idx = blockIdx.x * 256 + threadIdx.x;          // float4 index
    const int row = idx / (QKVN / 4);
    const int c4  = idx - row * (QKVN / 4);
    const int col = c4 * 4;
    const int h = col / 192;
    const int rem = col - h * 192;
    const int part = rem >> 6;
    const int d = rem & 63;

    float4 v = *reinterpret_cast<const float4*>(qkv + (size_t)row * QKVN + col);
    if (part == 0) { v.x *= 0.125f; v.y *= 0.125f; v.z *= 0.125f; v.w *= 0.125f; }

    __nv_bfloat16* dh = (part == 0) ? Qh : (part == 1) ? Kh : Vh;
    __nv_bfloat16* dl = (part == 0) ? Ql : (part == 1) ? Kl : Vl;

    const int b = row >> 11;          // / SS
    const int s = row & (SS - 1);
    const size_t o = (((size_t)(b * HH + h)) * SS + s) * HD + d;

    __nv_bfloat16 h0 = __float2bfloat16_rn(v.x);
    __nv_bfloat16 h1 = __float2bfloat16_rn(v.y);
    __nv_bfloat16 h2 = __float2bfloat16_rn(v.z);
    __nv_bfloat16 h3 = __float2bfloat16_rn(v.w);
    __nv_bfloat16 l0 = __float2bfloat16_rn(v.x - __bfloat162float(h0));
    __nv_bfloat16 l1 = __float2bfloat16_rn(v.y - __bfloat162float(h1));
    __nv_bfloat16 l2 = __float2bfloat16_rn(v.z - __bfloat162float(h2));
    __nv_bfloat16 l3 = __float2bfloat16_rn(v.w - __bfloat162float(h3));

    __nv_bfloat162* ph = reinterpret_cast<__nv_bfloat162*>(dh + o);
    __nv_bfloat162* pl = reinterpret_cast<__nv_bfloat162*>(dl + o);
    __nv_bfloat162 a; a.x = h0; a.y = h1;
    __nv_bfloat162 bq; bq.x = h2; bq.y = h3;
    ph[0] = a; ph[1] = bq;
    a.x = l0; a.y = l1; bq.x = l2; bq.y = l3;
    pl[0] = a; pl[1] = bq;
}

// ---------------------------------------------------------------------------
// bf16 mma.sync GEMM (unchanged from R5, proven)
// ---------------------------------------------------------------------------
__device__ __forceinline__ void load_stage(
    uint32_t sstage, const __nv_bfloat16* __restrict__ A,
    const __nv_bfloat16* __restrict__ B,
    int bm, int bn, int k0, int Kel, int tid)
{
    #pragma unroll
    for (int i = 0; i < 2; ++i) {
        const int idx = tid + i * 256;
        const int row = idx >> 2, ch = idx & 3;
        cp_async16(sstage + row * ROWPITCH + ch * 16,
                   A + (size_t)(bm + row) * Kel + k0 + ch * 8);
        cp_async16(sstage + ATILE_B + row * ROWPITCH + ch * 16,
                   B + (size_t)(bn + row) * Kel + k0 + ch * 8);
    }
}

__global__ __launch_bounds__(256) void gemm_mma(
    const __nv_bfloat16* __restrict__ A, const __nv_bfloat16* __restrict__ B,
    const float* __restrict__ bias, float* __restrict__ C,
    int N, int Kel)
{
    extern __shared__ __align__(128) char smem[];
    const uint32_t sb = smem_u32(smem);
    const int tid  = threadIdx.x;
    const int lane = tid & 31;
    const int wid  = tid >> 5;
    const int wm   = wid >> 1;
    const int wn   = wid & 1;
    const int bm = blockIdx.y * 128;
    const int bn = blockIdx.x * 128;
    const int kIters = Kel / BKI;

    uint32_t aOff[2];
    {
        const int arow = wm * 32 + (lane & 15);
        #pragma unroll
        for (int t = 0; t < 2; ++t)
            aOff[t] = (uint32_t)((arow + t * 16) * ROWPITCH + (lane >> 4) * 16);
    }
    uint32_t bOff[4];
    {
        #pragma unroll
        for (int p = 0; p < 4; ++p) {
            const int brow = wn * 64 + p * 16 + (lane & 7) + ((lane >> 4) & 1) * 8;
            bOff[p] = (uint32_t)(ATILE_B + brow * ROWPITCH + ((lane >> 3) & 1) * 16);
        }
    }

    float acc[2][8][4];
    #pragma unroll
    for (int mt = 0; mt < 2; ++mt)
        #pragma unroll
        for (int nt = 0; nt < 8; ++nt)
            #pragma unroll
            for (int r = 0; r < 4; ++r) acc[mt][nt][r] = 0.0f;

    #pragma unroll
    for (int s = 0; s < NSTG - 1; ++s) {
        load_stage(sb + s * STG_B, A, B, bm, bn, s * BKI, Kel, tid);
        cp_commit();
    }
    cp_wait<NSTG - 2>();
    __syncthreads();

    int cur = 0;
    for (int i = 0; i < kIters; ++i) {
        if (i + NSTG - 1 < kIters) {
            const int s = (cur + NSTG - 1) % NSTG;
            load_stage(sb + s * STG_B, A, B, bm, bn, (i + NSTG - 1) * BKI, Kel, tid);
        }
        cp_commit();

        const uint32_t st = sb + cur * STG_B;
        #pragma unroll
        for (int kb = 0; kb < 2; ++kb) {
            uint32_t a[2][4], br[8][2];
            #pragma unroll
            for (int t = 0; t < 2; ++t)
                ldmx4(a[t], st + aOff[t] + kb * 32);
            #pragma unroll
            for (int p = 0; p < 4; ++p) {
                uint32_t r[4];
                ldmx4(r, st + bOff[p] + kb * 32);
                br[p * 2 + 0][0] = r[0]; br[p * 2 + 0][1] = r[1];
                br[p * 2 + 1][0] = r[2]; br[p * 2 + 1][1] = r[3];
            }
            #pragma unroll
            for (int mt = 0; mt < 2; ++mt)
                #pragma unroll
                for (int nt = 0; nt < 8; ++nt)
                    mma16816(acc[mt][nt], a[mt], br[nt]);
        }

        cp_wait<NSTG - 2>();
        __syncthreads();
        cur = (cur + 1) % NSTG;
    }

    const int g  = lane >> 2;
    const int tq = lane & 3;
    #pragma unroll
    for (int mt = 0; mt < 2; ++mt) {
        #pragma unroll
        for (int rh = 0; rh < 2; ++rh) {
            const int row = bm + wm * 32 + mt * 16 + g + rh * 8;
            float* crow = C + (size_t)row * N;
            #pragma unroll
            for (int nt = 0; nt < 8; ++nt) {
                const int col = bn + wn * 64 + nt * 8 + tq * 2;
                float2 bs = *reinterpret_cast<const float2*>(bias + col);
                float2 o;
                o.x = acc[mt][nt][rh * 2 + 0] + bs.x;
                o.y = acc[mt][nt][rh * 2 + 1] + bs.y;
                *reinterpret_cast<float2*>(crow + col) = o;
            }
        }
    }
}

// ---------------------------------------------------------------------------
// Tensor-core flash attention (causal).
// CTA: 128 queries x one (b,h); 8 warps x m16. k-tile = 64 keys.
// S = Qhi@Khi + Qlo@Khi + Qhi@Klo ; O += Phi@Vhi + Plo@Vhi + Phi@Vlo.
// ---------------------------------------------------------------------------
__device__ __forceinline__ void load_att_stage(
    uint32_t dst, const __nv_bfloat16* __restrict__ Kh,
    const __nv_bfloat16* __restrict__ Kl,
    const __nv_bfloat16* __restrict__ Vh,
    const __nv_bfloat16* __restrict__ Vl,
    int bh, int key0, int tid)
{
    const int rr = tid >> 3;            // 0..31
    const int cc = tid & 7;             // 16B chunk
    const size_t src0 = ((size_t)bh * SS + key0 + rr) * HD + cc * 8;
    const size_t src1 = src0 + 32 * HD;
    const uint32_t d0 = dst + rr * AT_ROWP + cc * 16;
    const uint32_t d1 = d0 + 32 * AT_ROWP;
    cp_async16(d0,                  Kh + src0);
    cp_async16(d1,                  Kh + src1);
    cp_async16(d0 + AT_TILE_B,      Kl + src0);
    cp_async16(d1 + AT_TILE_B,      Kl + src1);
    cp_async16(d0 + 2 * AT_TILE_B,  Vh + src0);
    cp_async16(d1 + 2 * AT_TILE_B,  Vh + src1);
    cp_async16(d0 + 3 * AT_TILE_B,  Vl + src0);
    cp_async16(d1 + 3 * AT_TILE_B,  Vl + src1);
}

__global__ __launch_bounds__(256, 1) void attn_mma(
    const __nv_bfloat16* __restrict__ Qh, const __nv_bfloat16* __restrict__ Ql,
    const __nv_bfloat16* __restrict__ Kh, const __nv_bfloat16* __restrict__ Kl,
    const __nv_bfloat16* __restrict__ Vh, const __nv_bfloat16* __restrict__ Vl,
    float* __restrict__ attn_out)
{
    extern __shared__ __align__(128) char smem[];
    const uint32_t sb = smem_u32(smem);
    const int tid  = threadIdx.x;
    const int lane = tid & 31;
    const int w    = tid >> 5;
    const int g    = lane >> 2;
    const int tq   = lane & 3;

    const int qt = (gridDim.x - 1) - blockIdx.x;   // big tiles first
    const int h  = blockIdx.y;
    const int b  = blockIdx.z;
    const int bh = b * HH + h;
    const int qbase = qt * 128;
    const int nkt = 2 * qt + 2;

    // Q a-frags direct from gmem (persistent in regs)
    uint32_t qah[4][4], qal[4][4];
    {
        const __nv_bfloat16* qh0 = Qh + ((size_t)bh * SS + qbase + w * 16) * HD;
        const __nv_bfloat16* ql0 = Ql + ((size_t)bh * SS + qbase + w * 16) * HD;
        #pragma unroll
        for (int kc = 0; kc < 4; ++kc) {
            const int c0 = kc * 16 + tq * 2;
            qah[kc][0] = *reinterpret_cast<const uint32_t*>(qh0 + g * HD + c0);
            qah[kc][1] = *reinterpret_cast<const uint32_t*>(qh0 + (g + 8) * HD + c0);
            qah[kc][2] = *reinterpret_cast<const uint32_t*>(qh0 + g * HD + c0 + 8);
            qah[kc][3] = *reinterpret_cast<const uint32_t*>(qh0 + (g + 8) * HD + c0 + 8);
            qal[kc][0] = *reinterpret_cast<const uint32_t*>(ql0 + g * HD + c0);
            qal[kc][1] = *reinterpret_cast<const uint32_t*>(ql0 + (g + 8) * HD + c0);
            qal[kc][2] = *reinterpret_cast<const uint32_t*>(ql0 + g * HD + c0 + 8);
            qal[kc][3] = *reinterpret_cast<const uint32_t*>(ql0 + (g + 8) * HD + c0 + 8);
        }
    }

    float m0 = -1e30f, m1 = -1e30f, l0 = 0.0f, l1 = 0.0f;
    float O[8][4];
    #pragma unroll
    for (int nf = 0; nf < 8; ++nf)
        #pragma unroll
        for (int e = 0; e < 4; ++e) O[nf][e] = 0.0f;

    // ldmatrix offsets (exact GEMM b-frag pattern)
    uint32_t koff[4];
    #pragma unroll
    for (int np = 0; np < 4; ++np)
        koff[np] = (uint32_t)((np * 16 + (lane & 7) + ((lane >> 4) & 1) * 8) * AT_ROWP
                              + ((lane >> 3) & 1) * 16);
    uint32_t voff[4][4];
    #pragma unroll
    for (int kc2 = 0; kc2 < 4; ++kc2)
        #pragma unroll
        for (int np = 0; np < 4; ++np)
            voff[kc2][np] = (uint32_t)((kc2 * 16 + (lane & 7) + ((lane >> 3) & 1) * 8) * AT_ROWP
                                       + (np * 16 + ((lane >> 4) & 1) * 8) * 2);

    // pipeline prologue (nkt >= 2 always)
    load_att_stage(sb, Kh, Kl, Vh, Vl, bh, 0, tid);
    cp_commit();
    load_att_stage(sb + AT_STG_B, Kh, Kl, Vh, Vl, bh, 64, tid);
    cp_commit();
    cp_wait<1>();
    __syncthreads();

    int cur = 0;
    for (int kt = 0; kt < nkt; ++kt) {
        if (kt + 2 < nkt) {
            load_att_stage(sb + ((cur + 2) % AT_NSTG) * AT_STG_B,
                           Kh, Kl, Vh, Vl, bh, (kt + 2) * 64, tid);
        }
        cp_commit();

        const uint32_t st = sb + cur * AT_STG_B;

        // ---- S = Q @ K^T (3-term) ----
        float sacc[8][4];
        #pragma unroll
        for (int nf = 0; nf < 8; ++nf)
            #pragma unroll
            for (int e = 0; e < 4; ++e) sacc[nf][e] = 0.0f;

        #pragma unroll
        for (int kc = 0; kc < 4; ++kc) {
            #pragma unroll
            for (int np = 0; np < 4; ++np) {
                uint32_t kh[4], kl[4];
                ldmx4(kh, st + koff[np] + kc * 32);
                ldmx4(kl, st + AT_TILE_B + koff[np] + kc * 32);
                mma16816(sacc[2 * np],     qah[kc], kh);
                mma16816(sacc[2 * np],     qal[kc], kh);
                mma16816(sacc[2 * np],     qah[kc], kl);
                mma16816(sacc[2 * np + 1], qah[kc], kh + 2);
                mma16816(sacc[2 * np + 1], qal[kc], kh + 2);
                mma16816(sacc[2 * np + 1], qah[kc], kl + 2);
            }
        }

        // ---- causal mask (diagonal tiles only) ----
        if (kt >= 2 * qt) {
            const int key0 = kt * 64;
            const int r0 = qbase + w * 16 + g;
            #pragma unroll
            for (int nf = 0; nf < 8; ++nf) {
                const int c0 = key0 + nf * 8 + tq * 2;
                if (c0     > r0)     sacc[nf][0] = -1e30f;
                if (c0 + 1 > r0)     sacc[nf][1] = -1e30f;
                if (c0     > r0 + 8) sacc[nf][2] = -1e30f;
                if (c0 + 1 > r0 + 8) sacc[nf][3] = -1e30f;
            }
        }

        // ---- online softmax (rows g and g+8) ----
        float tm0 = -1e30f, tm1 = -1e30f;
        #pragma unroll
        for (int nf = 0; nf < 8; ++nf) {
            tm0 = fmaxf(tm0, fmaxf(sacc[nf][0], sacc[nf][1]));
            tm1 = fmaxf(tm1, fmaxf(sacc[nf][2], sacc[nf][3]));
        }
        tm0 = fmaxf(tm0, __shfl_xor_sync(0xffffffffu, tm0, 1));
        tm0 = fmaxf(tm0, __shfl_xor_sync(0xffffffffu, tm0, 2));
        tm1 = fmaxf(tm1, __shfl_xor_sync(0xffffffffu, tm1, 1));
        tm1 = fmaxf(tm1, __shfl_xor_sync(0xffffffffu, tm1, 2));
        const float mn0 = fmaxf(m0, tm0);
        const float mn1 = fmaxf(m1, tm1);
        const float cr0 = __expf(m0 - mn0);
        const float cr1 = __expf(m1 - mn1);
        m0 = mn0; m1 = mn1;

        float rs0 = 0.0f, rs1 = 0.0f;
        uint32_t pah[4][4], pal[4][4];
        #pragma unroll
        for (int nf = 0; nf < 8; ++nf) {
            float p0 = __expf(sacc[nf][0] - mn0);
            float p1 = __expf(sacc[nf][1] - mn0);
            float p2 = __expf(sacc[nf][2] - mn1);
            float p3 = __expf(sacc[nf][3] - mn1);
            rs0 += p0 + p1; rs1 += p2 + p3;
            const int kc2 = nf >> 1;
            const int o = (nf & 1) ? 2 : 0;
            // hi parts
            float h0f = __bfloat162float(__float2bfloat16_rn(p0));
            float h1f = __bfloat162float(__float2bfloat16_rn(p1));
            float h2f = __bfloat162float(__float2bfloat16_rn(p2));
            float h3f = __bfloat162float(__float2bfloat16_rn(p3));
            pah[kc2][o]     = pack_bf2(h0f, h1f);
            pah[kc2][o + 1] = pack_bf2(h2f, h3f);
            pal[kc2][o]     = pack_bf2(p0 - h0f, p1 - h1f);
            pal[kc2][o + 1] = pack_bf2(p2 - h2f, p3 - h3f);
        }
        rs0 += __shfl_xor_sync(0xffffffffu, rs0, 1);
        rs0 += __shfl_xor_sync(0xffffffffu, rs0, 2);
        rs1 += __shfl_xor_sync(0xffffffffu, rs1, 1);
        rs1 += __shfl_xor_sync(0xffffffffu, rs1, 2);
        l0 = l0 * cr0 + rs0;
        l1 = l1 * cr1 + rs1;
        #pragma unroll
        for (int nf = 0; nf < 8; ++nf) {
            O[nf][0] *= cr0; O[nf][1] *= cr0;
            O[nf][2] *= cr1; O[nf][3] *= cr1;
        }

        // ---- O += P @ V (3-term), V via ldmatrix.trans ----
        #pragma unroll
        for (int kc2 = 0; kc2 < 4; ++kc2) {
            #pragma unroll
            for (int np = 0; np < 4; ++np) {
                uint32_t vh[4], vl[4];
                ldmx4t(vh, st + 2 * AT_TILE_B + voff[kc2][np]);
                ldmx4t(vl, st + 3 * AT_TILE_B + voff[kc2][np]);
                mma16816(O[2 * np],     pah[kc2], vh);
                mma16816(O[2 * np],     pal[kc2], vh);
                mma16816(O[2 * np],     pah[kc2], vl);
                mma16816(O[2 * np + 1], pah[kc2], vh + 2);
                mma16816(O[2 * np + 1], pal[kc2], vh + 2);
                mma16816(O[2 * np + 1], pah[kc2], vl + 2);
            }
        }

        cp_wait<1>();
        __syncthreads();
        cur = (cur + 1) % AT_NSTG;
    }

    // ---- epilogue ----
    const float i0 = 1.0f / l0;
    const float i1 = 1.0f / l1;
    const int r0 = qbase + w * 16 + g;
    float* o0 = attn_out + ((size_t)(b * SS + r0)) * EE + h * HD;
    float* o1 = o0 + 8 * EE;
    #pragma unroll
    for (int nf = 0; nf < 8; ++nf) {
        float2 a, c;
        a.x = O[nf][0] * i0; a.y = O[nf][1] * i0;
        c.x = O[nf][2] * i1; c.y = O[nf][3] * i1;
        *reinterpret_cast<float2*>(o0 + nf * 8 + tq * 2) = a;
        *reinterpret_cast<float2*>(o1 + nf * 8 + tq * 2) = c;
    }
}

// ---------------------------------------------------------------------------
// Launch
// ---------------------------------------------------------------------------
extern "C" void kernel_launch(void* const* d_in, const int* in_sizes, int n_in,
                              void* d_out, int out_size)
{
    const float* x      = (const float*)d_in[0];
    const float* qkv_w  = (const float*)d_in[1];
    const float* qkv_b  = (const float*)d_in[2];
    const float* out_w  = (const float*)d_in[3];
    const float* out_b  = (const float*)d_in[4];
    float* out = (float*)d_out;

    float *qkv_ptr, *attn_ptr;
    __nv_bfloat16 *a1, *b1, *a2, *b2, *Qh, *Ql, *Kh, *Kl, *Vh, *Vl;
    cudaGetSymbolAddress((void**)&qkv_ptr, g_qkv);
    cudaGetSymbolAddress((void**)&attn_ptr, g_attn);
    cudaGetSymbolAddress((void**)&a1, g_a1);
    cudaGetSymbolAddress((void**)&b1, g_b1);
    cudaGetSymbolAddress((void**)&a2, g_a2);
    cudaGetSymbolAddress((void**)&b2, g_b2);
    cudaGetSymbolAddress((void**)&Qh, g_Qh);
    cudaGetSymbolAddress((void**)&Ql, g_Ql);
    cudaGetSymbolAddress((void**)&Kh, g_Kh);
    cudaGetSymbolAddress((void**)&Kl, g_Kl);
    cudaGetSymbolAddress((void**)&Vh, g_Vh);
    cudaGetSymbolAddress((void**)&Vl, g_Vl);

    cudaFuncSetAttribute(gemm_mma, cudaFuncAttributeMaxDynamicSharedMemorySize, GEMM_SMEM);
    cudaFuncSetAttribute(attn_mma, cudaFuncAttributeMaxDynamicSharedMemorySize, ATT_SMEM);

    // 1) split prep for proj1
    split_kernel<0><<<MROWS * EE / 512, 256>>>(x, a1, EE);
    split_kernel<1><<<QKVN  * EE / 512, 256>>>(qkv_w, b1, EE);

    // 2) QKV projection
    {
        dim3 grid(QKVN / 128, MROWS / 128);
        gemm_mma<<<grid, 256, GEMM_SMEM>>>(a1, b1, qkv_b, qkv_ptr, QKVN, KSPLIT);
    }

    // 3) convert QKV to per-head bf16 hi/lo
    qkv_convert<<<MROWS * QKVN / 1024, 256>>>(qkv_ptr, Qh, Ql, Kh, Kl, Vh, Vl);

    // 4) tensor-core causal flash attention
    {
        dim3 grid(SS / 128, HH, BB);
        attn_mma<<<grid, 256, ATT_SMEM>>>(Qh, Ql, Kh, Kl, Vh, Vl, attn_ptr);
    }

    // 5) split prep for proj2
    split_kernel<0><<<MROWS * EE / 512, 256>>>(attn_ptr, a2, EE);
    split_kernel<1><<<EE    * EE / 512, 256>>>(out_w, b2, EE);

    // 6) Output projection
    {
        dim3 grid(EE / 128, MROWS / 128);
        gemm_mma<<<grid, 256, GEMM_SMEM>>>(a2, b2, out_b, out, EE, KSPLIT);
    }
}